// round 12
// baseline (speedup 1.0000x reference)
#include <cuda_runtime.h>
#include <cuda_fp16.h>
#include <cstdint>

// ---------------- problem constants ----------------
#define BATCH   16384
#define INDIM   219
#define HID     64
#define CI      8           // inputs per chunk
#define CK      80          // k per chunk: 8 bases + 64 splines + 8 pad
#define NCH     28
#define KTOT    (NCH * CK)  // 2240
#define MROWS   64
#define THREADS 256
#define AS      88          // A smem row stride in fp16 elems -> 176 B
#define WS      72          // W smem row stride in fp16 elems -> 144 B
#define WHALF   11520       // 80 k * 144 B
#define WBUF    23040       // hi + lo
#define ABUF    11264       // 64 rows * 176 B

// Pre-split fp16 W chunk images: [chunk][hi 11520 | lo 11520]
__device__ __align__(16) unsigned char Wimg[NCH * WBUF];

// ---------------- smem layout ----------------
#define SM_SIDX 0                          // 64*4 = 256
#define SM_A    256                        // 3 bufs x 11264 = 33792
#define SM_W    (SM_A + 3 * ABUF)          // 3 bufs x 23040 = 69120
#define SMEM_TOTAL (SM_W + 3 * WBUF)       // 103168

// ---------------- PTX helpers ----------------
__device__ __forceinline__ uint32_t smem_u32(const void* p) {
    uint32_t a;
    asm("{ .reg .u64 t; cvta.to.shared.u64 t, %1; cvt.u32.u64 %0, t; }"
        : "=r"(a) : "l"(p));
    return a;
}
__device__ __forceinline__ void ldsm4(uint32_t* d, uint32_t addr) {
    asm volatile("ldmatrix.sync.aligned.m8n8.x4.shared.b16 {%0,%1,%2,%3}, [%4];"
                 : "=r"(d[0]), "=r"(d[1]), "=r"(d[2]), "=r"(d[3]) : "r"(addr));
}
__device__ __forceinline__ void ldsm4t(uint32_t* d, uint32_t addr) {
    asm volatile("ldmatrix.sync.aligned.m8n8.x4.trans.shared.b16 {%0,%1,%2,%3}, [%4];"
                 : "=r"(d[0]), "=r"(d[1]), "=r"(d[2]), "=r"(d[3]) : "r"(addr));
}
__device__ __forceinline__ void mma16816(float* c, const uint32_t* a,
                                         uint32_t b0, uint32_t b1) {
    asm volatile("mma.sync.aligned.m16n8k16.row.col.f32.f16.f16.f32 "
                 "{%0,%1,%2,%3}, {%4,%5,%6,%7}, {%8,%9}, {%0,%1,%2,%3};"
                 : "+f"(c[0]), "+f"(c[1]), "+f"(c[2]), "+f"(c[3])
                 : "r"(a[0]), "r"(a[1]), "r"(a[2]), "r"(a[3]), "r"(b0), "r"(b1));
}
__device__ __forceinline__ void cp16(uint32_t dst, const void* src) {
    asm volatile("cp.async.cg.shared.global [%0], [%1], 16;" :: "r"(dst), "l"(src));
}
#define BAR_SYNC(id)   asm volatile("bar.sync %0, 256;"   :: "r"(id) : "memory")
#define BAR_ARRIVE(id) asm volatile("bar.arrive %0, 256;" :: "r"(id) : "memory")

// ---------------- math helpers ----------------
__device__ __forceinline__ float siluf(float x) { return x / (1.0f + __expf(-x)); }

// Exact closed form of the reference Cox-de Boor cubic recursion on the
// uniform extended grid (knots -2.2 + 0.4*j).
__device__ __forceinline__ void spline_local(float x, int& m, float& n0, float& n1,
                                             float& n2, float& n3) {
    float tt = (x + 2.2f) * 2.5f;
    float mf = floorf(tt);
    m = (int)mf;
    float u = tt - mf, v = 1.0f - u;
    float u2 = u * u, u3 = u2 * u;
    n0 = v * v * v * (1.0f / 6.0f);
    n1 = (3.0f * u3 - 6.0f * u2 + 4.0f) * (1.0f / 6.0f);
    n2 = (-3.0f * u3 + 3.0f * u2 + 3.0f * u + 1.0f) * (1.0f / 6.0f);
    n3 = u3 * (1.0f / 6.0f);
}
// v[0] = silu, v[1..8] = spline basis values
__device__ __forceinline__ void fill_slots(float x, float* v) {
    v[0] = siluf(x);
    int m; float n0, n1, n2, n3;
    spline_local(x, m, n0, n1, n2, n3);
    if (m >= 0 && m <= 10) {
        int j0 = m - 3;
        if (m >= 3)           v[1 + j0]     = n0;
        if (m >= 2 && m <= 9) v[1 + j0 + 1] = n1;
        if (m >= 1 && m <= 8) v[1 + j0 + 2] = n2;
        if (m <= 7)           v[1 + m]      = n3;
    }
}
__device__ __forceinline__ uint32_t pack2h(float a, float b) {
    __half2 h = __floats2half2_rn(a, b);
    return *reinterpret_cast<uint32_t*>(&h);
}
__device__ __forceinline__ float fetch_x(int i, int rb,
                                         const float* __restrict__ hist,
                                         const float* __restrict__ statf,
                                         const float* __restrict__ timef,
                                         const float* __restrict__ emb, int sid) {
    if (i < 192) return hist[rb * 192 + i];
    if (i < 195) return statf[rb * 3 + (i - 192)];
    if (i < 203) return timef[rb * 8 + (i - 195)];
    return emb[sid * 16 + (i - 203)];
}

// ---------------- W repack: fp16 hi/lo split, chunked, padded rows ----------------
__global__ void repack_kernel(const float* __restrict__ wb1, const float* __restrict__ c1) {
    int idx = blockIdx.x * blockDim.x + threadIdx.x;
    if (idx >= KTOT * WS) return;
    int k = idx / WS, n = idx - (idx / WS) * WS;
    int chunk = k / CK, kl = k - chunk * CK;
    float val = 0.0f;
    if (n < HID) {
        if (kl < 8) {                       // base slots
            int i = chunk * CI + kl;
            if (i < INDIM) val = wb1[i * HID + n];
        } else if (kl < 72) {               // spline slots
            int q = kl - 8;
            int i = chunk * CI + (q >> 3), g = q & 7;
            if (i < INDIM) val = c1[(i * HID + n) * 8 + g];
        }                                    // kl 72..79: pad = 0
    }
    __half h = __float2half_rn(val);
    __half l = __float2half_rn(val - __half2float(h));
    unsigned char* base = Wimg + (size_t)chunk * WBUF + kl * (WS * 2) + n * 2;
    *reinterpret_cast<__half*>(base) = h;
    *reinterpret_cast<__half*>(base + WHALF) = l;
}

// ---------------- A-chunk builder: 4 cells per producer thread ----------------
__device__ __forceinline__ void build_chunk(unsigned char* abuf, int c,
                                            int pt, int row0, const int* sidx,
                                            const float* __restrict__ hist,
                                            const float* __restrict__ statf,
                                            const float* __restrict__ timef,
                                            const float* __restrict__ emb) {
    const int row = pt & 63;
    const int bgrp = pt >> 6;                // 0/1 -> inputs bgrp*4..+3
    const int i0 = c * CI + bgrp * 4;
    const int rb = row0 + row;
    float xv[4];
    if (i0 + 3 < 192) {
        float4 f = *reinterpret_cast<const float4*>(hist + (size_t)rb * 192 + i0);
        xv[0] = f.x; xv[1] = f.y; xv[2] = f.z; xv[3] = f.w;
    } else {
        int sid = sidx[row];
#pragma unroll
        for (int j = 0; j < 4; j++) {
            int i = i0 + j;
            xv[j] = (i < INDIM) ? fetch_x(i, rb, hist, statf, timef, emb, sid) : 0.0f;
        }
    }
    unsigned char* ar = abuf + row * (AS * 2);
    float fb[4];
#pragma unroll
    for (int j = 0; j < 4; j++) {
        float v[9];
#pragma unroll
        for (int s = 0; s < 9; s++) v[s] = 0.0f;
        if (i0 + j < INDIM) fill_slots(xv[j], v);
        fb[j] = v[0];
        int il = bgrp * 4 + j;
        *reinterpret_cast<uint4*>(ar + 16 + il * 16) =
            make_uint4(pack2h(v[1], v[2]), pack2h(v[3], v[4]),
                       pack2h(v[5], v[6]), pack2h(v[7], v[8]));
    }
    *reinterpret_cast<uint2*>(ar + bgrp * 8) =
        make_uint2(pack2h(fb[0], fb[1]), pack2h(fb[2], fb[3]));
    if (bgrp == 0)
        *reinterpret_cast<uint4*>(ar + 144) = make_uint4(0u, 0u, 0u, 0u);
}

// ---------------- main fused kernel: producer/consumer warp specialization ----
extern __shared__ __align__(16) unsigned char smem[];

__global__ __launch_bounds__(THREADS, 2)
void kan_main(const float* __restrict__ hist, const float* __restrict__ statf,
              const float* __restrict__ timef, const int* __restrict__ st_idx,
              const float* __restrict__ emb, const float* __restrict__ wb2,
              const float* __restrict__ c2, float* __restrict__ out) {
    const uint32_t sbase = smem_u32(smem);
    const int t = threadIdx.x;
    const int lane = t & 31;
    const int wid = t >> 5;
    const int row0 = blockIdx.x * MROWS;
    int* sidx = reinterpret_cast<int*>(smem + SM_SIDX);

    if (t < MROWS) sidx[t] = st_idx[row0 + t];
    __syncthreads();

    float acc[2][4][4];
#pragma unroll
    for (int mt = 0; mt < 2; mt++)
#pragma unroll
        for (int nt = 0; nt < 4; nt++)
#pragma unroll
            for (int e = 0; e < 4; e++) acc[mt][nt][e] = 0.0f;

    if (wid >= 4) {
        // ================= PRODUCER warps (4-7) =================
        const int pt = t - 128;
        for (int c = 0; c < NCH; c++) {
            const int s = c % 3;
            if (c >= 3) BAR_SYNC(4 + s);          // wait buffer free
            // stream W(c)
            {
                const unsigned char* src = Wimg + (size_t)c * WBUF;
                uint32_t d = sbase + SM_W + (uint32_t)s * WBUF;
                for (int n = pt; n < WBUF / 16; n += 128)
                    cp16(d + n * 16, src + n * 16);
                asm volatile("cp.async.commit_group;");
            }
            // build A(c)
            build_chunk(smem + SM_A + s * ABUF, c, pt, row0, sidx,
                        hist, statf, timef, emb);
            asm volatile("cp.async.wait_group 0;");
            asm volatile("membar.cta;");
            BAR_ARRIVE(1 + s);                    // publish full
        }
    } else {
        // ================= CONSUMER warps (0-3) =================
        const int wm = wid >> 1;          // rows wm*32
        const int wn = wid & 1;           // cols wn*32
        const int arow = wm * 32 + (lane & 15);
        const int acolh = (lane >> 4) * 8;
        const int bj = lane >> 3, bw = lane & 7;

        for (int c = 0; c < NCH; c++) {
            const int s = c % 3;
            BAR_SYNC(1 + s);                      // wait full (fence)
            const uint32_t aA = sbase + SM_A + (uint32_t)s * ABUF;
            const uint32_t aW = sbase + SM_W + (uint32_t)s * WBUF;

            uint32_t ah[2][2][4], bhh[2][2][4], bll[2][2][4];
            // load frags for ks into register slot
            auto load_frags = [&](int slot, int ks) {
                int kcol = ks * 16 + acolh;
#pragma unroll
                for (int mt = 0; mt < 2; mt++)
                    ldsm4(ah[slot][mt], aA + ((arow + mt * 16) * AS + kcol) * 2);
                int kk = ks * 16 + (bj & 1) * 8 + bw;
#pragma unroll
                for (int nt2 = 0; nt2 < 2; nt2++) {
                    int n = wn * 32 + nt2 * 16 + (bj >> 1) * 8;
                    uint32_t bd = kk * (WS * 2) + n * 2;
                    ldsm4t(bhh[slot][nt2], aW + bd);
                    ldsm4t(bll[slot][nt2], aW + WHALF + bd);
                }
            };
            load_frags(0, 0);
#pragma unroll
            for (int ks = 0; ks < 5; ks++) {
                const int cur = ks & 1, nxt = cur ^ 1;
                if (ks < 4) load_frags(nxt, ks + 1);
#pragma unroll
                for (int mt = 0; mt < 2; mt++)
#pragma unroll
                    for (int nt = 0; nt < 4; nt++) {
                        uint32_t b0h = bhh[cur][nt >> 1][(nt & 1) * 2];
                        uint32_t b1h = bhh[cur][nt >> 1][(nt & 1) * 2 + 1];
                        uint32_t b0l = bll[cur][nt >> 1][(nt & 1) * 2];
                        uint32_t b1l = bll[cur][nt >> 1][(nt & 1) * 2 + 1];
                        mma16816(acc[mt][nt], ah[cur][mt], b0h, b1h);
                        mma16816(acc[mt][nt], ah[cur][mt], b0l, b1l);
                    }
            }
            BAR_ARRIVE(4 + s);                    // release empty
        }
    }
    __syncthreads();   // all producers + consumers done

    // ---- write h to smem (reuse A region), then layer 2 ----
    float* h = reinterpret_cast<float*>(smem + SM_A);   // h[64][66]
    if (wid < 4) {
        const int wm = wid >> 1, wn = wid & 1;
#pragma unroll
        for (int mt = 0; mt < 2; mt++)
#pragma unroll
            for (int nt = 0; nt < 4; nt++) {
                int r0 = wm * 32 + mt * 16 + (lane >> 2);
                int col = wn * 32 + nt * 8 + (lane & 3) * 2;
                *reinterpret_cast<float2*>(&h[r0 * 66 + col]) =
                    make_float2(acc[mt][nt][0], acc[mt][nt][1]);
                *reinterpret_cast<float2*>(&h[(r0 + 8) * 66 + col]) =
                    make_float2(acc[mt][nt][2], acc[mt][nt][3]);
            }
    }
    __syncthreads();

    {
        const int row = t >> 2;
        const int sub = t & 3;
        float accum = 0.0f;
#pragma unroll
        for (int kk = 0; kk < 16; kk++) {
            int o = sub + kk * 4;
            float xv = h[row * 66 + o];
            float v = siluf(xv) * __ldg(&wb2[o]);
            int m; float n0, n1, n2, n3;
            spline_local(xv, m, n0, n1, n2, n3);
            if (m >= 0 && m <= 10) {
                int j0 = m - 3;
                if (m >= 3)           v += n0 * __ldg(&c2[o * 8 + j0]);
                if (m >= 2 && m <= 9) v += n1 * __ldg(&c2[o * 8 + j0 + 1]);
                if (m >= 1 && m <= 8) v += n2 * __ldg(&c2[o * 8 + j0 + 2]);
                if (m <= 7)           v += n3 * __ldg(&c2[o * 8 + m]);
            }
            accum += v;
        }
        accum += __shfl_xor_sync(0xffffffffu, accum, 1);
        accum += __shfl_xor_sync(0xffffffffu, accum, 2);
        if (sub == 0) out[row0 + row] = accum;
    }
}

// ---------------- launch ----------------
extern "C" void kernel_launch(void* const* d_in, const int* in_sizes, int n_in,
                              void* d_out, int out_size) {
    const float* hist  = (const float*)d_in[0];
    const float* statf = (const float*)d_in[1];
    const float* timef = (const float*)d_in[2];
    const int*   sti   = (const int*)  d_in[3];
    const float* emb   = (const float*)d_in[4];
    const float* wb1   = (const float*)d_in[5];
    const float* c1    = (const float*)d_in[6];
    const float* wb2   = (const float*)d_in[7];
    const float* c2    = (const float*)d_in[8];
    float* out = (float*)d_out;

    static int configured = 0;
    if (!configured) {
        cudaFuncSetAttribute(kan_main, cudaFuncAttributeMaxDynamicSharedMemorySize,
                             SMEM_TOTAL);
        configured = 1;
    }
    repack_kernel<<<(KTOT * WS + 255) / 256, 256>>>(wb1, c1);
    kan_main<<<BATCH / MROWS, THREADS, SMEM_TOTAL>>>(hist, statf, timef, sti, emb,
                                                     wb2, c2, out);
}

// round 14
// speedup vs baseline: 1.2205x; 1.2205x over previous
#include <cuda_runtime.h>
#include <cuda_fp16.h>
#include <cstdint>

// ---------------- problem constants ----------------
#define BATCH   16384
#define INDIM   219
#define HID     64
#define CI      8           // inputs per chunk
#define CK      80          // k per chunk: 8 bases + 64 splines + 8 pad
#define NCH     28
#define KTOT    (NCH * CK)  // 2240
#define MROWS   32          // batch rows per block
#define THREADS 128
#define AS      88          // A smem row stride in fp16 elems -> 176 B (16-aligned!)
#define WS      72          // W smem row stride in fp16 elems -> 144 B
#define WBUF    11520       // 80 k * 144 B (single fp16, no residual)
#define ABUF    5632        // 32 rows * 176 B

// fp16 W chunk images (single precision term)
__device__ __align__(16) unsigned char Wimg[NCH * WBUF];   // 322.5 KB

// ---------------- smem layout ----------------
#define SM_SIDX 0                          // 32*4 = 128 (pad to 256)
#define SM_A    256                        // 2 bufs x 5632 = 11264
#define SM_W    (SM_A + 2 * ABUF)          // 3 bufs x 11520 = 34560
#define SMEM_TOTAL (SM_W + 3 * WBUF)       // 46080 (45 KB) -> 4 blocks/SM

// ---------------- PTX helpers ----------------
__device__ __forceinline__ uint32_t smem_u32(const void* p) {
    uint32_t a;
    asm("{ .reg .u64 t; cvta.to.shared.u64 t, %1; cvt.u32.u64 %0, t; }"
        : "=r"(a) : "l"(p));
    return a;
}
__device__ __forceinline__ void ldsm4(uint32_t* d, uint32_t addr) {
    asm volatile("ldmatrix.sync.aligned.m8n8.x4.shared.b16 {%0,%1,%2,%3}, [%4];"
                 : "=r"(d[0]), "=r"(d[1]), "=r"(d[2]), "=r"(d[3]) : "r"(addr));
}
__device__ __forceinline__ void ldsm4t(uint32_t* d, uint32_t addr) {
    asm volatile("ldmatrix.sync.aligned.m8n8.x4.trans.shared.b16 {%0,%1,%2,%3}, [%4];"
                 : "=r"(d[0]), "=r"(d[1]), "=r"(d[2]), "=r"(d[3]) : "r"(addr));
}
__device__ __forceinline__ void mma16816(float* c, const uint32_t* a,
                                         uint32_t b0, uint32_t b1) {
    asm volatile("mma.sync.aligned.m16n8k16.row.col.f32.f16.f16.f32 "
                 "{%0,%1,%2,%3}, {%4,%5,%6,%7}, {%8,%9}, {%0,%1,%2,%3};"
                 : "+f"(c[0]), "+f"(c[1]), "+f"(c[2]), "+f"(c[3])
                 : "r"(a[0]), "r"(a[1]), "r"(a[2]), "r"(a[3]), "r"(b0), "r"(b1));
}
__device__ __forceinline__ void cp16(uint32_t dst, const void* src) {
    asm volatile("cp.async.cg.shared.global [%0], [%1], 16;" :: "r"(dst), "l"(src));
}

// ---------------- math helpers ----------------
__device__ __forceinline__ float siluf(float x) { return x / (1.0f + __expf(-x)); }

// Exact closed form of the reference Cox-de Boor cubic recursion on the
// uniform extended grid (knots -2.2 + 0.4*j).
__device__ __forceinline__ void spline_local(float x, int& m, float& n0, float& n1,
                                             float& n2, float& n3) {
    float tt = (x + 2.2f) * 2.5f;
    float mf = floorf(tt);
    m = (int)mf;
    float u = tt - mf, v = 1.0f - u;
    float u2 = u * u, u3 = u2 * u;
    n0 = v * v * v * (1.0f / 6.0f);
    n1 = (3.0f * u3 - 6.0f * u2 + 4.0f) * (1.0f / 6.0f);
    n2 = (-3.0f * u3 + 3.0f * u2 + 3.0f * u + 1.0f) * (1.0f / 6.0f);
    n3 = u3 * (1.0f / 6.0f);
}
// v[0] = silu, v[1..8] = spline basis values
__device__ __forceinline__ void fill_slots(float x, float* v) {
    v[0] = siluf(x);
    int m; float n0, n1, n2, n3;
    spline_local(x, m, n0, n1, n2, n3);
    if (m >= 0 && m <= 10) {
        int j0 = m - 3;
        if (m >= 3)           v[1 + j0]     = n0;
        if (m >= 2 && m <= 9) v[1 + j0 + 1] = n1;
        if (m >= 1 && m <= 8) v[1 + j0 + 2] = n2;
        if (m <= 7)           v[1 + m]      = n3;
    }
}
__device__ __forceinline__ uint32_t pack2h(float a, float b) {
    __half2 h = __floats2half2_rn(a, b);
    return *reinterpret_cast<uint32_t*>(&h);
}
__device__ __forceinline__ float fetch_x(int i, int rb,
                                         const float* __restrict__ hist,
                                         const float* __restrict__ statf,
                                         const float* __restrict__ timef,
                                         const float* __restrict__ emb, int sid) {
    if (i < 192) return hist[rb * 192 + i];
    if (i < 195) return statf[rb * 3 + (i - 192)];
    if (i < 203) return timef[rb * 8 + (i - 195)];
    return emb[sid * 16 + (i - 203)];
}

// ---------------- W repack: single fp16, chunked, padded rows ----------------
__global__ void repack_kernel(const float* __restrict__ wb1, const float* __restrict__ c1) {
    int idx = blockIdx.x * blockDim.x + threadIdx.x;
    if (idx >= KTOT * WS) return;
    int k = idx / WS, n = idx - (idx / WS) * WS;
    int chunk = k / CK, kl = k - chunk * CK;
    float val = 0.0f;
    if (n < HID) {
        if (kl < 8) {                       // base slots
            int i = chunk * CI + kl;
            if (i < INDIM) val = wb1[i * HID + n];
        } else if (kl < 72) {               // spline slots
            int q = kl - 8;
            int i = chunk * CI + (q >> 3), g = q & 7;
            if (i < INDIM) val = c1[(i * HID + n) * 8 + g];
        }                                    // kl 72..79: pad = 0
    }
    *reinterpret_cast<__half*>(Wimg + (size_t)chunk * WBUF + kl * (WS * 2) + n * 2) =
        __float2half_rn(val);
}

// ---------------- A-chunk builder: 2 cells per thread ----------------
__device__ __forceinline__ void build_chunk(unsigned char* abuf, int c,
                                            int t, int row0, const int* sidx,
                                            const float* __restrict__ hist,
                                            const float* __restrict__ statf,
                                            const float* __restrict__ timef,
                                            const float* __restrict__ emb) {
    const int row = t & 31;
    const int ip = t >> 5;                   // 0..3 -> inputs ip*2, ip*2+1
    const int i0 = c * CI + ip * 2;
    const int rb = row0 + row;
    float xv[2];
    if (i0 + 1 < 192) {
        float2 f = *reinterpret_cast<const float2*>(hist + (size_t)rb * 192 + i0);
        xv[0] = f.x; xv[1] = f.y;
    } else {
        int sid = sidx[row];
#pragma unroll
        for (int j = 0; j < 2; j++) {
            int i = i0 + j;
            xv[j] = (i < INDIM) ? fetch_x(i, rb, hist, statf, timef, emb, sid) : 0.0f;
        }
    }
    unsigned char* ar = abuf + row * (AS * 2);   // 176 B stride, 16-aligned
    float fb[2];
#pragma unroll
    for (int j = 0; j < 2; j++) {
        float v[9];
#pragma unroll
        for (int s = 0; s < 9; s++) v[s] = 0.0f;
        if (i0 + j < INDIM) fill_slots(xv[j], v);
        fb[j] = v[0];
        int il = ip * 2 + j;                 // 0..7
        *reinterpret_cast<uint4*>(ar + 16 + il * 16) =
            make_uint4(pack2h(v[1], v[2]), pack2h(v[3], v[4]),
                       pack2h(v[5], v[6]), pack2h(v[7], v[8]));
    }
    // 2 bases -> one 4B store
    *reinterpret_cast<uint32_t*>(ar + ip * 4) = pack2h(fb[0], fb[1]);
    // pad slots 72..79 -> zero
    if (ip == 0)
        *reinterpret_cast<uint4*>(ar + 144) = make_uint4(0u, 0u, 0u, 0u);
}

// ---------------- main fused kernel ----------------
extern __shared__ __align__(16) unsigned char smem[];

__global__ __launch_bounds__(THREADS)
void kan_main(const float* __restrict__ hist, const float* __restrict__ statf,
              const float* __restrict__ timef, const int* __restrict__ st_idx,
              const float* __restrict__ emb, const float* __restrict__ wb2,
              const float* __restrict__ c2, float* __restrict__ out) {
    const uint32_t sbase = smem_u32(smem);
    const int t = threadIdx.x;
    const int lane = t & 31;
    const int wid = t >> 5;
    const int wm = wid >> 1;          // rows wm*16
    const int wn = wid & 1;           // cols wn*32
    const int row0 = blockIdx.x * MROWS;
    int* sidx = reinterpret_cast<int*>(smem + SM_SIDX);

    if (t < MROWS) sidx[t] = st_idx[row0 + t];

    // prologue: W(0), W(1) in flight
    {
        for (int n = t; n < WBUF / 16; n += THREADS)
            cp16(sbase + SM_W + n * 16, Wimg + n * 16);
        asm volatile("cp.async.commit_group;");
        for (int n = t; n < WBUF / 16; n += THREADS)
            cp16(sbase + SM_W + WBUF + n * 16, Wimg + WBUF + n * 16);
        asm volatile("cp.async.commit_group;");
    }
    // build A(0) (chunk 0 is hist-only; sidx becomes visible via loop-top sync)
    build_chunk(smem + SM_A, 0, t, row0, sidx, hist, statf, timef, emb);

    float acc[4][4];
#pragma unroll
    for (int nt = 0; nt < 4; nt++)
#pragma unroll
        for (int e = 0; e < 4; e++) acc[nt][e] = 0.0f;

    const int arow = wm * 16 + (lane & 15);
    const int acolh = (lane >> 4) * 8;
    const int bj = lane >> 3, bw = lane & 7;

    for (int c = 0; c < NCH; c++) {
        asm volatile("cp.async.wait_group 1;");
        __syncthreads();   // A(c) built, W(c) resident, prior readers done

        // overlap: build A(c+1) + issue W(c+2) + MMA(c)
        if (c + 1 < NCH)
            build_chunk(smem + SM_A + ((c + 1) & 1) * ABUF, c + 1,
                        t, row0, sidx, hist, statf, timef, emb);
        if (c + 2 < NCH) {
            const unsigned char* s = Wimg + (size_t)(c + 2) * WBUF;
            uint32_t d = sbase + SM_W + (uint32_t)((c + 2) % 3) * WBUF;
            for (int n = t; n < WBUF / 16; n += THREADS)
                cp16(d + n * 16, s + n * 16);
        }
        asm volatile("cp.async.commit_group;");

        const uint32_t aA = sbase + SM_A + (uint32_t)(c & 1) * ABUF;
        const uint32_t aW = sbase + SM_W + (uint32_t)(c % 3) * WBUF;
#pragma unroll
        for (int ks = 0; ks < 5; ks++) {
            uint32_t ah[4], bh[2][4];
            ldsm4(ah, aA + (arow * AS + ks * 16 + acolh) * 2);
            int kk = ks * 16 + (bj & 1) * 8 + bw;
#pragma unroll
            for (int nt2 = 0; nt2 < 2; nt2++) {
                int n = wn * 32 + nt2 * 16 + (bj >> 1) * 8;
                ldsm4t(bh[nt2], aW + kk * (WS * 2) + n * 2);
            }
#pragma unroll
            for (int nt = 0; nt < 4; nt++)
                mma16816(acc[nt], ah,
                         bh[nt >> 1][(nt & 1) * 2], bh[nt >> 1][(nt & 1) * 2 + 1]);
        }
        __syncthreads();   // MMA(c) done before A(c&1)/W(c%3) overwritten
    }

    // ---- write h to smem (reuse A region), then layer 2 ----
    __syncthreads();
    float* h = reinterpret_cast<float*>(smem + SM_A);   // h[32][66]
#pragma unroll
    for (int nt = 0; nt < 4; nt++) {
        int r0 = wm * 16 + (lane >> 2);
        int col = wn * 32 + nt * 8 + (lane & 3) * 2;
        *reinterpret_cast<float2*>(&h[r0 * 66 + col]) =
            make_float2(acc[nt][0], acc[nt][1]);
        *reinterpret_cast<float2*>(&h[(r0 + 8) * 66 + col]) =
            make_float2(acc[nt][2], acc[nt][3]);
    }
    __syncthreads();

    {
        const int row = t >> 2;
        const int sub = t & 3;
        float accum = 0.0f;
#pragma unroll
        for (int kk = 0; kk < 16; kk++) {
            int o = sub + kk * 4;
            float xv = h[row * 66 + o];
            float v = siluf(xv) * __ldg(&wb2[o]);
            int m; float n0, n1, n2, n3;
            spline_local(xv, m, n0, n1, n2, n3);
            if (m >= 0 && m <= 10) {
                int j0 = m - 3;
                if (m >= 3)           v += n0 * __ldg(&c2[o * 8 + j0]);
                if (m >= 2 && m <= 9) v += n1 * __ldg(&c2[o * 8 + j0 + 1]);
                if (m >= 1 && m <= 8) v += n2 * __ldg(&c2[o * 8 + j0 + 2]);
                if (m <= 7)           v += n3 * __ldg(&c2[o * 8 + m]);
            }
            accum += v;
        }
        accum += __shfl_xor_sync(0xffffffffu, accum, 1);
        accum += __shfl_xor_sync(0xffffffffu, accum, 2);
        if (sub == 0) out[row0 + row] = accum;
    }
}

// ---------------- launch ----------------
extern "C" void kernel_launch(void* const* d_in, const int* in_sizes, int n_in,
                              void* d_out, int out_size) {
    const float* hist  = (const float*)d_in[0];
    const float* statf = (const float*)d_in[1];
    const float* timef = (const float*)d_in[2];
    const int*   sti   = (const int*)  d_in[3];
    const float* emb   = (const float*)d_in[4];
    const float* wb1   = (const float*)d_in[5];
    const float* c1    = (const float*)d_in[6];
    const float* wb2   = (const float*)d_in[7];
    const float* c2    = (const float*)d_in[8];
    float* out = (float*)d_out;

    static int configured = 0;
    if (!configured) {
        cudaFuncSetAttribute(kan_main, cudaFuncAttributeMaxDynamicSharedMemorySize,
                             SMEM_TOTAL);
        configured = 1;
    }
    repack_kernel<<<(KTOT * WS + 255) / 256, 256>>>(wb1, c1);
    kan_main<<<BATCH / MROWS, THREADS, SMEM_TOTAL>>>(hist, statf, timef, sti, emb,
                                                     wb2, c2, out);
}

// round 15
// speedup vs baseline: 1.3373x; 1.0957x over previous
#include <cuda_runtime.h>
#include <cuda_fp16.h>
#include <cstdint>

// ---------------- problem constants ----------------
#define BATCH   16384
#define INDIM   219
#define HID     64
#define CI      8           // inputs per chunk
#define CK      80          // k per chunk: 8 bases + 64 splines + 8 pad
#define NCH     28
#define KTOT    (NCH * CK)  // 2240
#define MROWS   32          // batch rows per block
#define THREADS 128
#define AS      88          // A smem row stride in fp16 elems -> 176 B (16-aligned)
#define WS      72          // W smem row stride in fp16 elems -> 144 B
#define WBUF    11520       // 80 k * 144 B (single fp16)
#define ABUF    5632        // 32 rows * 176 B

// fp16 W chunk images
__device__ __align__(16) unsigned char Wimg[NCH * WBUF];   // 322.5 KB

// ---------------- smem layout ----------------
#define SM_SIDX 0                          // 32*4 (pad to 256)
#define SM_A    256                        // 2 bufs x 5632 = 11264
#define SM_W    (SM_A + 2 * ABUF)          // 3 bufs x 11520 = 34560
#define SMEM_TOTAL (SM_W + 3 * WBUF)       // 46080 B

// ---------------- PTX helpers ----------------
__device__ __forceinline__ uint32_t smem_u32(const void* p) {
    uint32_t a;
    asm("{ .reg .u64 t; cvta.to.shared.u64 t, %1; cvt.u32.u64 %0, t; }"
        : "=r"(a) : "l"(p));
    return a;
}
__device__ __forceinline__ void ldsm4(uint32_t* d, uint32_t addr) {
    asm volatile("ldmatrix.sync.aligned.m8n8.x4.shared.b16 {%0,%1,%2,%3}, [%4];"
                 : "=r"(d[0]), "=r"(d[1]), "=r"(d[2]), "=r"(d[3]) : "r"(addr));
}
__device__ __forceinline__ void ldsm4t(uint32_t* d, uint32_t addr) {
    asm volatile("ldmatrix.sync.aligned.m8n8.x4.trans.shared.b16 {%0,%1,%2,%3}, [%4];"
                 : "=r"(d[0]), "=r"(d[1]), "=r"(d[2]), "=r"(d[3]) : "r"(addr));
}
__device__ __forceinline__ void mma16816(float* c, const uint32_t* a,
                                         uint32_t b0, uint32_t b1) {
    asm volatile("mma.sync.aligned.m16n8k16.row.col.f32.f16.f16.f32 "
                 "{%0,%1,%2,%3}, {%4,%5,%6,%7}, {%8,%9}, {%0,%1,%2,%3};"
                 : "+f"(c[0]), "+f"(c[1]), "+f"(c[2]), "+f"(c[3])
                 : "r"(a[0]), "r"(a[1]), "r"(a[2]), "r"(a[3]), "r"(b0), "r"(b1));
}
__device__ __forceinline__ void cp16(uint32_t dst, const void* src) {
    asm volatile("cp.async.cg.shared.global [%0], [%1], 16;" :: "r"(dst), "l"(src));
}

// ---------------- math helpers ----------------
__device__ __forceinline__ float siluf(float x) { return x / (1.0f + __expf(-x)); }

// Exact closed form of the reference Cox-de Boor cubic recursion on the
// uniform extended grid (knots -2.2 + 0.4*j).
__device__ __forceinline__ void spline_local(float x, int& m, float& n0, float& n1,
                                             float& n2, float& n3) {
    float tt = (x + 2.2f) * 2.5f;
    float mf = floorf(tt);
    m = (int)mf;
    float u = tt - mf, v = 1.0f - u;
    float u2 = u * u, u3 = u2 * u;
    n0 = v * v * v * (1.0f / 6.0f);
    n1 = (3.0f * u3 - 6.0f * u2 + 4.0f) * (1.0f / 6.0f);
    n2 = (-3.0f * u3 + 3.0f * u2 + 3.0f * u + 1.0f) * (1.0f / 6.0f);
    n3 = u3 * (1.0f / 6.0f);
}
__device__ __forceinline__ void fill_slots(float x, float* v) {
    v[0] = siluf(x);
    int m; float n0, n1, n2, n3;
    spline_local(x, m, n0, n1, n2, n3);
    if (m >= 0 && m <= 10) {
        int j0 = m - 3;
        if (m >= 3)           v[1 + j0]     = n0;
        if (m >= 2 && m <= 9) v[1 + j0 + 1] = n1;
        if (m >= 1 && m <= 8) v[1 + j0 + 2] = n2;
        if (m <= 7)           v[1 + m]      = n3;
    }
}
__device__ __forceinline__ uint32_t pack2h(float a, float b) {
    __half2 h = __floats2half2_rn(a, b);
    return *reinterpret_cast<uint32_t*>(&h);
}
__device__ __forceinline__ float fetch_x(int i, int rb,
                                         const float* __restrict__ hist,
                                         const float* __restrict__ statf,
                                         const float* __restrict__ timef,
                                         const float* __restrict__ emb, int sid) {
    if (i < 192) return hist[rb * 192 + i];
    if (i < 195) return statf[rb * 3 + (i - 192)];
    if (i < 203) return timef[rb * 8 + (i - 195)];
    return emb[sid * 16 + (i - 203)];
}

// ---------------- W repack: single fp16, chunked, padded rows ----------------
__global__ void repack_kernel(const float* __restrict__ wb1, const float* __restrict__ c1) {
    int idx = blockIdx.x * blockDim.x + threadIdx.x;
    if (idx >= KTOT * WS) return;
    int k = idx / WS, n = idx - (idx / WS) * WS;
    int chunk = k / CK, kl = k - chunk * CK;
    float val = 0.0f;
    if (n < HID) {
        if (kl < 8) {
            int i = chunk * CI + kl;
            if (i < INDIM) val = wb1[i * HID + n];
        } else if (kl < 72) {
            int q = kl - 8;
            int i = chunk * CI + (q >> 3), g = q & 7;
            if (i < INDIM) val = c1[(i * HID + n) * 8 + g];
        }                                    // kl 72..79: pad = 0
    }
    *reinterpret_cast<__half*>(Wimg + (size_t)chunk * WBUF + kl * (WS * 2) + n * 2) =
        __float2half_rn(val);
}

// ---------------- x loader (coalesced mapping: row = t>>2, ip = t&3) --------
__device__ __forceinline__ float2 load_x2(int c, int t, int row0, const int* sidx,
                                          const float* __restrict__ hist,
                                          const float* __restrict__ statf,
                                          const float* __restrict__ timef,
                                          const float* __restrict__ emb) {
    const int row = t >> 2, ip = t & 3;
    const int i0 = c * CI + ip * 2;
    const int rb = row0 + row;
    if (i0 + 1 < 192)
        return *reinterpret_cast<const float2*>(hist + (size_t)rb * 192 + i0);
    float2 r;
    int sid = sidx[row];
    r.x = (i0 < INDIM)     ? fetch_x(i0, rb, hist, statf, timef, emb, sid) : 0.0f;
    r.y = (i0 + 1 < INDIM) ? fetch_x(i0 + 1, rb, hist, statf, timef, emb, sid) : 0.0f;
    return r;
}

// ---------------- activation store (after MMA; x already in regs) -----------
__device__ __forceinline__ void store_act(unsigned char* abuf, float2 xv, int c,
                                          int t) {
    const int row = t >> 2, ip = t & 3;
    const int i0 = c * CI + ip * 2;
    unsigned char* ar = abuf + row * (AS * 2);
    float fb[2];
    float xs[2] = {xv.x, xv.y};
#pragma unroll
    for (int j = 0; j < 2; j++) {
        float v[9];
#pragma unroll
        for (int s = 0; s < 9; s++) v[s] = 0.0f;
        if (i0 + j < INDIM) fill_slots(xs[j], v);
        fb[j] = v[0];
        int il = ip * 2 + j;
        *reinterpret_cast<uint4*>(ar + 16 + il * 16) =
            make_uint4(pack2h(v[1], v[2]), pack2h(v[3], v[4]),
                       pack2h(v[5], v[6]), pack2h(v[7], v[8]));
    }
    *reinterpret_cast<uint32_t*>(ar + ip * 4) = pack2h(fb[0], fb[1]);
    if (ip == 0)
        *reinterpret_cast<uint4*>(ar + 144) = make_uint4(0u, 0u, 0u, 0u);
}

// ---------------- main fused kernel ----------------
extern __shared__ __align__(16) unsigned char smem[];

__global__ __launch_bounds__(THREADS)
void kan_main(const float* __restrict__ hist, const float* __restrict__ statf,
              const float* __restrict__ timef, const int* __restrict__ st_idx,
              const float* __restrict__ emb, const float* __restrict__ wb2,
              const float* __restrict__ c2, float* __restrict__ out) {
    const uint32_t sbase = smem_u32(smem);
    const int t = threadIdx.x;
    const int lane = t & 31;
    const int wid = t >> 5;
    const int wm = wid >> 1;          // rows wm*16
    const int wn = wid & 1;           // cols wn*32
    const int row0 = blockIdx.x * MROWS;
    int* sidx = reinterpret_cast<int*>(smem + SM_SIDX);

    if (t < MROWS) sidx[t] = st_idx[row0 + t];

    // prologue: W(0), W(1) in flight
    {
        for (int n = t; n < WBUF / 16; n += THREADS)
            cp16(sbase + SM_W + n * 16, Wimg + n * 16);
        asm volatile("cp.async.commit_group;");
        for (int n = t; n < WBUF / 16; n += THREADS)
            cp16(sbase + SM_W + WBUF + n * 16, Wimg + WBUF + n * 16);
        asm volatile("cp.async.commit_group;");
    }
    // build A(0) (hist-only chunk; sidx not needed until chunk 25)
    {
        float2 x0 = load_x2(0, t, row0, sidx, hist, statf, timef, emb);
        store_act(smem + SM_A, x0, 0, t);
    }

    float acc[4][4];
#pragma unroll
    for (int nt = 0; nt < 4; nt++)
#pragma unroll
        for (int e = 0; e < 4; e++) acc[nt][e] = 0.0f;

    const int arow = wm * 16 + (lane & 15);
    const int acolh = (lane >> 4) * 8;
    const int bj = lane >> 3, bw = lane & 7;

    for (int c = 0; c < NCH; c++) {
        asm volatile("cp.async.wait_group 1;");
        __syncthreads();   // A(c) stores visible, W(c) resident, old readers done

        // 1) issue next-chunk x loads (latency hides under MMA)
        float2 xn = make_float2(0.0f, 0.0f);
        if (c + 1 < NCH)
            xn = load_x2(c + 1, t, row0, sidx, hist, statf, timef, emb);

        // 2) issue W(c+2) cp.async (latency hides under MMA)
        if (c + 2 < NCH) {
            const unsigned char* s = Wimg + (size_t)(c + 2) * WBUF;
            uint32_t d = sbase + SM_W + (uint32_t)((c + 2) % 3) * WBUF;
            for (int n = t; n < WBUF / 16; n += THREADS)
                cp16(d + n * 16, s + n * 16);
        }
        asm volatile("cp.async.commit_group;");

        // 3) MMA(c), fragment double-buffered
        const uint32_t aA = sbase + SM_A + (uint32_t)(c & 1) * ABUF;
        const uint32_t aW = sbase + SM_W + (uint32_t)(c % 3) * WBUF;
        uint32_t ah[2][4], bh[2][2][4];
        {
            ldsm4(ah[0], aA + (arow * AS + acolh) * 2);
            int kk = (bj & 1) * 8 + bw;
#pragma unroll
            for (int nt2 = 0; nt2 < 2; nt2++)
                ldsm4t(bh[0][nt2], aW + kk * (WS * 2)
                                  + (wn * 32 + nt2 * 16 + (bj >> 1) * 8) * 2);
        }
#pragma unroll
        for (int ks = 0; ks < 5; ks++) {
            const int cur = ks & 1, nxt = cur ^ 1;
            if (ks < 4) {
                ldsm4(ah[nxt], aA + (arow * AS + (ks + 1) * 16 + acolh) * 2);
                int kk = (ks + 1) * 16 + (bj & 1) * 8 + bw;
#pragma unroll
                for (int nt2 = 0; nt2 < 2; nt2++)
                    ldsm4t(bh[nxt][nt2], aW + kk * (WS * 2)
                                        + (wn * 32 + nt2 * 16 + (bj >> 1) * 8) * 2);
            }
#pragma unroll
            for (int nt = 0; nt < 4; nt++)
                mma16816(acc[nt], ah[cur],
                         bh[cur][nt >> 1][(nt & 1) * 2],
                         bh[cur][nt >> 1][(nt & 1) * 2 + 1]);
        }

        // 4) convert + store A(c+1) (x regs have arrived during MMA)
        if (c + 1 < NCH)
            store_act(smem + SM_A + ((c + 1) & 1) * ABUF, xn, c + 1, t);
    }

    // ---- write h to smem (reuse A region), then layer 2 ----
    __syncthreads();
    float* h = reinterpret_cast<float*>(smem + SM_A);   // h[32][66]
#pragma unroll
    for (int nt = 0; nt < 4; nt++) {
        int r0 = wm * 16 + (lane >> 2);
        int col = wn * 32 + nt * 8 + (lane & 3) * 2;
        *reinterpret_cast<float2*>(&h[r0 * 66 + col]) =
            make_float2(acc[nt][0], acc[nt][1]);
        *reinterpret_cast<float2*>(&h[(r0 + 8) * 66 + col]) =
            make_float2(acc[nt][2], acc[nt][3]);
    }
    __syncthreads();

    {
        const int row = t >> 2;
        const int sub = t & 3;
        float accum = 0.0f;
#pragma unroll
        for (int kk = 0; kk < 16; kk++) {
            int o = sub + kk * 4;
            float xv = h[row * 66 + o];
            float v = siluf(xv) * __ldg(&wb2[o]);
            int m; float n0, n1, n2, n3;
            spline_local(xv, m, n0, n1, n2, n3);
            if (m >= 0 && m <= 10) {
                int j0 = m - 3;
                if (m >= 3)           v += n0 * __ldg(&c2[o * 8 + j0]);
                if (m >= 2 && m <= 9) v += n1 * __ldg(&c2[o * 8 + j0 + 1]);
                if (m >= 1 && m <= 8) v += n2 * __ldg(&c2[o * 8 + j0 + 2]);
                if (m <= 7)           v += n3 * __ldg(&c2[o * 8 + m]);
            }
            accum += v;
        }
        accum += __shfl_xor_sync(0xffffffffu, accum, 1);
        accum += __shfl_xor_sync(0xffffffffu, accum, 2);
        if (sub == 0) out[row0 + row] = accum;
    }
}

// ---------------- launch ----------------
extern "C" void kernel_launch(void* const* d_in, const int* in_sizes, int n_in,
                              void* d_out, int out_size) {
    const float* hist  = (const float*)d_in[0];
    const float* statf = (const float*)d_in[1];
    const float* timef = (const float*)d_in[2];
    const int*   sti   = (const int*)  d_in[3];
    const float* emb   = (const float*)d_in[4];
    const float* wb1   = (const float*)d_in[5];
    const float* c1    = (const float*)d_in[6];
    const float* wb2   = (const float*)d_in[7];
    const float* c2    = (const float*)d_in[8];
    float* out = (float*)d_out;

    static int configured = 0;
    if (!configured) {
        cudaFuncSetAttribute(kan_main, cudaFuncAttributeMaxDynamicSharedMemorySize,
                             SMEM_TOTAL);
        configured = 1;
    }
    repack_kernel<<<(KTOT * WS + 255) / 256, 256>>>(wb1, c1);
    kan_main<<<BATCH / MROWS, THREADS, SMEM_TOTAL>>>(hist, statf, timef, sti, emb,
                                                     wb2, c2, out);
}